// round 5
// baseline (speedup 1.0000x reference)
#include <cuda_runtime.h>
#include <cuda_fp16.h>

#define N_NODES 100000
#define N_EDGES 1600000
#define D 64
#define SCAN_BLK 1024
#define NB ((N_NODES + SCAN_BLK - 1) / SCAN_BLK)   // 98

// ---------------------------------------------------------------------------
// device scratch
// ---------------------------------------------------------------------------
__device__ __align__(16) __half2 g_supp_h[(size_t)N_NODES * 32];  // X@W fp16 (12.8 MB)
__device__ int                g_counts[N_NODES];     // histogram (zeroed by scan)
__device__ int                g_offs[N_NODES + 1];
__device__ int                g_cur[N_NODES];
__device__ unsigned long long g_state[NB];           // lookback state (zeroed by fill)
__device__ int2               g_csr[N_EDGES];

union U8 { uint2 u; __half2 h[2]; };
union F2U { unsigned long long u; float2 f; };

__device__ __forceinline__ void ffma2(unsigned long long& acc,
                                      unsigned long long a,
                                      unsigned long long b) {
    asm("fma.rn.f32x2 %0, %1, %2, %0;" : "+l"(acc) : "l"(a), "l"(b));
}

// ---------------------------------------------------------------------------
// Kernel 1: g_supp_h = fp16(X @ W) via packed f32x2 FMA; dst histogram fused.
// Accumulator u64 holds (sum over even k, sum over odd k); reduced at end.
// ---------------------------------------------------------------------------
__global__ void __launch_bounds__(256) gemm_hist_kernel(const float* __restrict__ x,
                                                        const float* __restrict__ w,
                                                        const int* __restrict__ dst) {
    __shared__ float Wt[64 * 66];    // Wt[c*66 + k] = w[k][c]   (transposed, 16.9 KB)
    __shared__ float Xs[128 * 66];   // stride 66 -> 8B-aligned LDS.64 at even k

    const int tid  = threadIdx.x;
    const int base = blockIdx.x * 128;

    // fused histogram (overlaps FMA-bound GEMM; g_counts zeroed by prior scan)
    {
        int stride = gridDim.x * 256;
        for (int e = blockIdx.x * 256 + tid; e < N_EDGES; e += stride)
            atomicAdd(&g_counts[dst[e]], 1);
    }

    // load W transposed: w[k][c] -> Wt[c][k]
    {
        const float4* w4 = (const float4*)w;
#pragma unroll
        for (int j = 0; j < 4; j++) {
            int idx = tid + j * 256;        // float4 index into w
            int k   = idx >> 4;
            int c4  = idx & 15;
            float4 v = w4[idx];
            Wt[(c4 * 4 + 0) * 66 + k] = v.x;
            Wt[(c4 * 4 + 1) * 66 + k] = v.y;
            Wt[(c4 * 4 + 2) * 66 + k] = v.z;
            Wt[(c4 * 4 + 3) * 66 + k] = v.w;
        }
    }
    // load X tile
    for (int j = tid; j < 128 * 16; j += 256) {
        int r  = j >> 4;
        int c4 = j & 15;
        int gr = base + r;
        float4 v = make_float4(0.f, 0.f, 0.f, 0.f);
        if (gr < N_NODES) v = ((const float4*)x)[gr * 16 + c4];
        float* dp = &Xs[r * 66 + c4 * 4];
        dp[0] = v.x; dp[1] = v.y; dp[2] = v.z; dp[3] = v.w;
    }
    __syncthreads();

    const int dg = tid & 7;
    const int rq = tid >> 3;

    unsigned long long acc2[4][8];
#pragma unroll
    for (int i = 0; i < 4; i++)
#pragma unroll
        for (int c = 0; c < 8; c++) acc2[i][c] = 0ULL;

    const float* wt0 = &Wt[(dg * 4) * 66];        // cols dg*4..+3
    const float* wt1 = &Wt[(32 + dg * 4) * 66];   // cols 32+dg*4..+3
    const float* xr  = &Xs[(rq * 4) * 66];

#pragma unroll 4
    for (int k = 0; k < 64; k += 2) {
        unsigned long long wp[8];
#pragma unroll
        for (int c = 0; c < 4; c++) {
            wp[c]     = *(const unsigned long long*)&wt0[c * 66 + k];
            wp[c + 4] = *(const unsigned long long*)&wt1[c * 66 + k];
        }
#pragma unroll
        for (int i = 0; i < 4; i++) {
            unsigned long long xp = *(const unsigned long long*)&xr[i * 66 + k];
#pragma unroll
            for (int c = 0; c < 8; c++) ffma2(acc2[i][c], wp[c], xp);
        }
    }

#pragma unroll
    for (int i = 0; i < 4; i++) {
        int r = base + rq * 4 + i;
        if (r < N_NODES) {
            float s[8];
#pragma unroll
            for (int c = 0; c < 8; c++) {
                F2U u; u.u = acc2[i][c];
                s[c] = u.f.x + u.f.y;
            }
            U8 a, b;
            a.h[0] = __floats2half2_rn(s[0], s[1]);
            a.h[1] = __floats2half2_rn(s[2], s[3]);
            b.h[0] = __floats2half2_rn(s[4], s[5]);
            b.h[1] = __floats2half2_rn(s[6], s[7]);
            *(uint2*)&g_supp_h[(size_t)r * 32 + dg * 2]      = a.u;
            *(uint2*)&g_supp_h[(size_t)r * 32 + 16 + dg * 2] = b.u;
        }
    }
}

// ---------------------------------------------------------------------------
// Kernel 2: single-pass exclusive scan with decoupled lookback.
// ---------------------------------------------------------------------------
__global__ void __launch_bounds__(SCAN_BLK) scan_kernel() {
    __shared__ int warp_sums[32];
    __shared__ int s_prefix;

    const int b    = blockIdx.x;
    const int i    = b * SCAN_BLK + threadIdx.x;
    const int lane = threadIdx.x & 31;
    const int wid  = threadIdx.x >> 5;

    int v = 0;
    if (i < N_NODES) { v = g_counts[i]; g_counts[i] = 0; }

    int s = v;
#pragma unroll
    for (int d = 1; d < 32; d <<= 1) {
        int t = __shfl_up_sync(0xffffffffu, s, d);
        if (lane >= d) s += t;
    }
    if (lane == 31) warp_sums[wid] = s;
    __syncthreads();

    if (wid == 0) {
        int ws = warp_sums[lane];
        int ss = ws;
#pragma unroll
        for (int d = 1; d < 32; d <<= 1) {
            int t = __shfl_up_sync(0xffffffffu, ss, d);
            if (lane >= d) ss += t;
        }
        warp_sums[lane] = ss - ws;
        if (lane == 31) atomicExch(&g_state[b], (1ULL << 32) | (unsigned)ss);

        int sum = 0;
        for (int p = lane; p < b; p += 32) {
            unsigned long long xv;
            do { xv = atomicAdd(&g_state[p], 0ULL); } while (!(xv >> 32));
            sum += (int)(unsigned)xv;
        }
#pragma unroll
        for (int d = 16; d >= 1; d >>= 1)
            sum += __shfl_xor_sync(0xffffffffu, sum, d);
        if (lane == 0) s_prefix = sum;
    }
    __syncthreads();

    if (i < N_NODES) {
        int o = s_prefix + warp_sums[wid] + (s - v);
        g_offs[i] = o;
        g_cur[i]  = o;
    }
    if (i == 0) g_offs[N_NODES] = N_EDGES;
}

// ---------------------------------------------------------------------------
// Kernel 3: fill CSR; re-zeroes lookback state.
// ---------------------------------------------------------------------------
__global__ void fill_kernel(const int* __restrict__ src,
                            const int* __restrict__ dst,
                            const float* __restrict__ adj) {
    if (blockIdx.x == 0 && threadIdx.x < NB) g_state[threadIdx.x] = 0ULL;
    int e = blockIdx.x * 256 + threadIdx.x;
    if (e < N_EDGES) {
        int p = atomicAdd(&g_cur[dst[e]], 1);
        g_csr[p] = make_int2(src[e], __float_as_int(adj[e]));
    }
}

// ---------------------------------------------------------------------------
// Kernel 4: gather, 8 lanes/node, edge loop unrolled x4 for MLP.
// ---------------------------------------------------------------------------
__device__ __forceinline__ void acc_edge(int2 ev, int l,
                                         float2& a0, float2& a1,
                                         float2& a2, float2& a3) {
    float v = __int_as_float(ev.y);
    union { uint4 u; __half2 h[4]; } r;
    r.u = *(const uint4*)(g_supp_h + ((size_t)ev.x << 5) + (l << 2));
    float2 f0 = __half22float2(r.h[0]), f1 = __half22float2(r.h[1]);
    float2 f2 = __half22float2(r.h[2]), f3 = __half22float2(r.h[3]);
    a0.x += v * f0.x;  a0.y += v * f0.y;
    a1.x += v * f1.x;  a1.y += v * f1.y;
    a2.x += v * f2.x;  a2.y += v * f2.y;
    a3.x += v * f3.x;  a3.y += v * f3.y;
}

__global__ void __launch_bounds__(256) gather_kernel(const float* __restrict__ bias,
                                                     float* __restrict__ out) {
    int tid  = blockIdx.x * 256 + threadIdx.x;
    int node = tid >> 3;
    int l    = tid & 7;

    int e0 = g_offs[node];
    int e1 = g_offs[node + 1];

    float2 a0 = make_float2(0.f, 0.f), a1 = a0, a2 = a0, a3 = a0;

    int e = e0;
    for (; e + 4 <= e1; e += 4) {
        int2 ev0 = __ldg(&g_csr[e]);
        int2 ev1 = __ldg(&g_csr[e + 1]);
        int2 ev2 = __ldg(&g_csr[e + 2]);
        int2 ev3 = __ldg(&g_csr[e + 3]);
        acc_edge(ev0, l, a0, a1, a2, a3);
        acc_edge(ev1, l, a0, a1, a2, a3);
        acc_edge(ev2, l, a0, a1, a2, a3);
        acc_edge(ev3, l, a0, a1, a2, a3);
    }
    for (; e < e1; e++) {
        int2 ev = __ldg(&g_csr[e]);
        acc_edge(ev, l, a0, a1, a2, a3);
    }

    float4 b0 = ((const float4*)bias)[l * 2];
    float4 b1 = ((const float4*)bias)[l * 2 + 1];
    float* op = out + (size_t)node * 64 + l * 8;
    *(float4*)op       = make_float4(a0.x + b0.x, a0.y + b0.y, a1.x + b0.z, a1.y + b0.w);
    *(float4*)(op + 4) = make_float4(a2.x + b1.x, a2.y + b1.y, a3.x + b1.z, a3.y + b1.w);
}

// ---------------------------------------------------------------------------
extern "C" void kernel_launch(void* const* d_in, const int* in_sizes, int n_in,
                              void* d_out, int out_size) {
    const float* x    = (const float*)d_in[0];
    const float* w    = (const float*)d_in[1];
    const float* bias = (const float*)d_in[2];
    const float* adj  = (const float*)d_in[3];
    const int*   src  = (const int*)d_in[4];
    const int*   dst  = (const int*)d_in[5];
    float*       out  = (float*)d_out;

    (void)in_sizes; (void)n_in; (void)out_size;

    const int eblk = (N_EDGES + 255) / 256;      // 6250

    gemm_hist_kernel<<<(N_NODES + 127) / 128, 256>>>(x, w, dst);
    scan_kernel<<<NB, SCAN_BLK>>>();
    fill_kernel<<<eblk, 256>>>(src, dst, adj);
    gather_kernel<<<(N_NODES * 8) / 256, 256>>>(bias, out);
}

// round 6
// speedup vs baseline: 1.1293x; 1.1293x over previous
#include <cuda_runtime.h>
#include <cuda_fp16.h>

#define N_NODES 100000
#define N_EDGES 1600000
#define D 64
#define SCAN_BLK 1024
#define NB ((N_NODES + SCAN_BLK - 1) / SCAN_BLK)   // 98

// ---------------------------------------------------------------------------
// device scratch
// ---------------------------------------------------------------------------
__device__ __align__(16) __half2 g_supp_h[(size_t)N_NODES * 32];  // X@W fp16 (12.8 MB)
__device__ int                g_counts[N_NODES];     // histogram (zeroed by scan)
__device__ int                g_offs[N_NODES + 1];
__device__ int                g_cur[N_NODES];
__device__ unsigned long long g_state[NB];           // lookback state (zeroed by fill)
__device__ int2               g_csr[N_EDGES];

union U8 { uint2 u; __half2 h[2]; };

// ---------------------------------------------------------------------------
// Side stream + fork/join events, created once at module init (host objects
// only — no device memory). kernel_launch does identical work every call.
// ---------------------------------------------------------------------------
static cudaStream_t g_s2 = nullptr;
static cudaEvent_t  g_evFork = nullptr, g_evJoin = nullptr;
struct HxStreamInit {
    HxStreamInit() {
        if (cudaStreamCreateWithFlags(&g_s2, cudaStreamNonBlocking) != cudaSuccess)
            g_s2 = nullptr;
        if (cudaEventCreateWithFlags(&g_evFork, cudaEventDisableTiming) != cudaSuccess)
            g_evFork = nullptr;
        if (cudaEventCreateWithFlags(&g_evJoin, cudaEventDisableTiming) != cudaSuccess)
            g_evJoin = nullptr;
    }
};
static HxStreamInit g_hx_stream_init;

// ---------------------------------------------------------------------------
// GEMM (round-3 proven body): g_supp_h = fp16(X @ W). Pure — no histogram.
// ---------------------------------------------------------------------------
__global__ void __launch_bounds__(256) gemm_kernel(const float* __restrict__ x,
                                                   const float* __restrict__ w) {
    __shared__ float Ws[64 * 64];
    __shared__ float Xs[128 * 65];

    const int tid  = threadIdx.x;
    const int base = blockIdx.x * 128;

    {
        const float4* w4  = (const float4*)w;
        float4*       Ws4 = (float4*)Ws;
#pragma unroll
        for (int j = 0; j < 4; j++) Ws4[tid + j * 256] = w4[tid + j * 256];
    }
    for (int j = tid; j < 128 * 16; j += 256) {
        int r  = j >> 4;
        int c4 = j & 15;
        int gr = base + r;
        float4 v = make_float4(0.f, 0.f, 0.f, 0.f);
        if (gr < N_NODES) v = ((const float4*)x)[gr * 16 + c4];
        float* dp = &Xs[r * 65 + c4 * 4];
        dp[0] = v.x; dp[1] = v.y; dp[2] = v.z; dp[3] = v.w;
    }
    __syncthreads();

    const int dg = tid & 7;
    const int rq = tid >> 3;

    float acc[4][8];
#pragma unroll
    for (int i = 0; i < 4; i++)
#pragma unroll
        for (int j = 0; j < 8; j++) acc[i][j] = 0.f;

#pragma unroll 8
    for (int k = 0; k < 64; k++) {
        float4 w0 = *(const float4*)&Ws[k * 64 + dg * 4];
        float4 w1 = *(const float4*)&Ws[k * 64 + 32 + dg * 4];
#pragma unroll
        for (int i = 0; i < 4; i++) {
            float xv = Xs[(rq * 4 + i) * 65 + k];
            acc[i][0] += xv * w0.x;  acc[i][1] += xv * w0.y;
            acc[i][2] += xv * w0.z;  acc[i][3] += xv * w0.w;
            acc[i][4] += xv * w1.x;  acc[i][5] += xv * w1.y;
            acc[i][6] += xv * w1.z;  acc[i][7] += xv * w1.w;
        }
    }

#pragma unroll
    for (int i = 0; i < 4; i++) {
        int r = base + rq * 4 + i;
        if (r < N_NODES) {
            U8 a, b;
            a.h[0] = __floats2half2_rn(acc[i][0], acc[i][1]);
            a.h[1] = __floats2half2_rn(acc[i][2], acc[i][3]);
            b.h[0] = __floats2half2_rn(acc[i][4], acc[i][5]);
            b.h[1] = __floats2half2_rn(acc[i][6], acc[i][7]);
            *(uint2*)&g_supp_h[(size_t)r * 32 + dg * 2]      = a.u;
            *(uint2*)&g_supp_h[(size_t)r * 32 + 16 + dg * 2] = b.u;
        }
    }
}

// ---------------------------------------------------------------------------
// CSR build chain (runs concurrently with the GEMM on the main stream)
// ---------------------------------------------------------------------------
__global__ void hist_kernel(const int* __restrict__ dst) {
    int e = blockIdx.x * 256 + threadIdx.x;
    if (e < N_EDGES) atomicAdd(&g_counts[dst[e]], 1);
}

__global__ void __launch_bounds__(SCAN_BLK) scan_kernel() {
    __shared__ int warp_sums[32];
    __shared__ int s_prefix;

    const int b    = blockIdx.x;
    const int i    = b * SCAN_BLK + threadIdx.x;
    const int lane = threadIdx.x & 31;
    const int wid  = threadIdx.x >> 5;

    int v = 0;
    if (i < N_NODES) { v = g_counts[i]; g_counts[i] = 0; }

    int s = v;
#pragma unroll
    for (int d = 1; d < 32; d <<= 1) {
        int t = __shfl_up_sync(0xffffffffu, s, d);
        if (lane >= d) s += t;
    }
    if (lane == 31) warp_sums[wid] = s;
    __syncthreads();

    if (wid == 0) {
        int ws = warp_sums[lane];
        int ss = ws;
#pragma unroll
        for (int d = 1; d < 32; d <<= 1) {
            int t = __shfl_up_sync(0xffffffffu, ss, d);
            if (lane >= d) ss += t;
        }
        warp_sums[lane] = ss - ws;
        if (lane == 31) atomicExch(&g_state[b], (1ULL << 32) | (unsigned)ss);

        int sum = 0;
        for (int p = lane; p < b; p += 32) {
            unsigned long long xv;
            do { xv = atomicAdd(&g_state[p], 0ULL); } while (!(xv >> 32));
            sum += (int)(unsigned)xv;
        }
#pragma unroll
        for (int d = 16; d >= 1; d >>= 1)
            sum += __shfl_xor_sync(0xffffffffu, sum, d);
        if (lane == 0) s_prefix = sum;
    }
    __syncthreads();

    if (i < N_NODES) {
        int o = s_prefix + warp_sums[wid] + (s - v);
        g_offs[i] = o;
        g_cur[i]  = o;
    }
    if (i == 0) g_offs[N_NODES] = N_EDGES;
}

__global__ void fill_kernel(const int* __restrict__ src,
                            const int* __restrict__ dst,
                            const float* __restrict__ adj) {
    if (blockIdx.x == 0 && threadIdx.x < NB) g_state[threadIdx.x] = 0ULL;
    int e = blockIdx.x * 256 + threadIdx.x;
    if (e < N_EDGES) {
        int p = atomicAdd(&g_cur[dst[e]], 1);
        g_csr[p] = make_int2(src[e], __float_as_int(adj[e]));
    }
}

// ---------------------------------------------------------------------------
// Gather: 8 lanes per dst node; edge loop unrolled x4 for MLP.
// ---------------------------------------------------------------------------
__device__ __forceinline__ void acc_edge(int2 ev, int l,
                                         float2& a0, float2& a1,
                                         float2& a2, float2& a3) {
    float v = __int_as_float(ev.y);
    union { uint4 u; __half2 h[4]; } r;
    r.u = *(const uint4*)(g_supp_h + ((size_t)ev.x << 5) + (l << 2));
    float2 f0 = __half22float2(r.h[0]), f1 = __half22float2(r.h[1]);
    float2 f2 = __half22float2(r.h[2]), f3 = __half22float2(r.h[3]);
    a0.x += v * f0.x;  a0.y += v * f0.y;
    a1.x += v * f1.x;  a1.y += v * f1.y;
    a2.x += v * f2.x;  a2.y += v * f2.y;
    a3.x += v * f3.x;  a3.y += v * f3.y;
}

__global__ void __launch_bounds__(256) gather_kernel(const float* __restrict__ bias,
                                                     float* __restrict__ out) {
    int tid  = blockIdx.x * 256 + threadIdx.x;
    int node = tid >> 3;
    int l    = tid & 7;

    int e0 = g_offs[node];
    int e1 = g_offs[node + 1];

    float2 a0 = make_float2(0.f, 0.f), a1 = a0, a2 = a0, a3 = a0;

    int e = e0;
    for (; e + 4 <= e1; e += 4) {
        int2 ev0 = __ldg(&g_csr[e]);
        int2 ev1 = __ldg(&g_csr[e + 1]);
        int2 ev2 = __ldg(&g_csr[e + 2]);
        int2 ev3 = __ldg(&g_csr[e + 3]);
        acc_edge(ev0, l, a0, a1, a2, a3);
        acc_edge(ev1, l, a0, a1, a2, a3);
        acc_edge(ev2, l, a0, a1, a2, a3);
        acc_edge(ev3, l, a0, a1, a2, a3);
    }
    for (; e < e1; e++) {
        int2 ev = __ldg(&g_csr[e]);
        acc_edge(ev, l, a0, a1, a2, a3);
    }

    float4 b0 = ((const float4*)bias)[l * 2];
    float4 b1 = ((const float4*)bias)[l * 2 + 1];
    float* op = out + (size_t)node * 64 + l * 8;
    *(float4*)op       = make_float4(a0.x + b0.x, a0.y + b0.y, a1.x + b0.z, a1.y + b0.w);
    *(float4*)(op + 4) = make_float4(a2.x + b1.x, a2.y + b1.y, a3.x + b1.z, a3.y + b1.w);
}

// ---------------------------------------------------------------------------
extern "C" void kernel_launch(void* const* d_in, const int* in_sizes, int n_in,
                              void* d_out, int out_size) {
    const float* x    = (const float*)d_in[0];
    const float* w    = (const float*)d_in[1];
    const float* bias = (const float*)d_in[2];
    const float* adj  = (const float*)d_in[3];
    const int*   src  = (const int*)d_in[4];
    const int*   dst  = (const int*)d_in[5];
    float*       out  = (float*)d_out;

    (void)in_sizes; (void)n_in; (void)out_size;

    const int eblk  = (N_EDGES + 255) / 256;        // 6250
    const int gblk  = (N_NODES + 127) / 128;        // 782

    const bool forked = (g_s2 != nullptr) && (g_evFork != nullptr) && (g_evJoin != nullptr);

    if (forked) {
        // fork: GEMM on side stream, CSR build on main stream, join before gather
        cudaEventRecord(g_evFork, 0);
        cudaStreamWaitEvent(g_s2, g_evFork, 0);
        gemm_kernel<<<gblk, 256, 0, g_s2>>>(x, w);
    } else {
        gemm_kernel<<<gblk, 256>>>(x, w);
    }

    hist_kernel<<<eblk, 256>>>(dst);
    scan_kernel<<<NB, SCAN_BLK>>>();
    fill_kernel<<<eblk, 256>>>(src, dst, adj);

    if (forked) {
        cudaEventRecord(g_evJoin, g_s2);
        cudaStreamWaitEvent(0, g_evJoin, 0);
    }

    gather_kernel<<<(N_NODES * 8) / 256, 256>>>(bias, out);
}